// round 4
// baseline (speedup 1.0000x reference)
#include <cuda_runtime.h>
#include <math.h>

#define NN 50000
#define FF 48
#define CC 16     // H*C1 with H=1 -> softmax == 1, attention vanishes
#define L1 8

// ---------------- device scratch ----------------
__device__ __align__(16) float g_y[NN * CC];    // x @ W
__device__ __align__(16) float g_agg[NN * CC];  // segment sum (self loop preloaded)
__device__ int   g_degi[NN];                    // in-degree + 1 (self loop)
__device__ int   g_is64;

// ---------------- detect edge dtype + zero deg + zero loss slot ----------------
// int64 node ids < 50000 => every odd 32-bit word of the first 1024 entries is 0.
__global__ void k_detect(const unsigned* __restrict__ ew, float* losss, int n) {
    int i = blockIdx.x * blockDim.x + threadIdx.x;
    if (i < n) g_degi[i] = 1;                 // self loop
    if (blockIdx.x == 0) {
        __shared__ unsigned any;
        if (threadIdx.x == 0) any = 0u;
        __syncthreads();
        unsigned v = 0u;
        for (int k = threadIdx.x; k < 1024; k += blockDim.x) v |= ew[2 * k + 1];
        if (v) atomicOr(&any, 1u);
        __syncthreads();
        if (threadIdx.x == 0) {
            g_is64 = (any == 0u) ? 1 : 0;
            if (losss) *losss = 0.0f;
        }
    }
}

// ---------------- fused: projection y = x @ W (smem-staged) + deg histogram ----------------
__global__ void k_proj_hist(const float* __restrict__ x, const float* __restrict__ W,
                            const void* __restrict__ ei, int n, int E, int projBlocks) {
    if ((int)blockIdx.x < projBlocks) {
        __shared__ float sW[FF * CC];   // 3 KB
        __shared__ float sX[16 * FF];   // 3 KB
        for (int i = threadIdx.x; i < FF * CC; i += blockDim.x) sW[i] = W[i];
        int nodeBase = blockIdx.x * 16;
        for (int i = threadIdx.x; i < 16 * FF; i += blockDim.x) {
            int g = nodeBase * FF + i;
            sX[i] = (g < n * FF) ? x[g] : 0.0f;
        }
        __syncthreads();
        int node = nodeBase + (threadIdx.x >> 4);
        int c    = threadIdx.x & 15;
        if (node >= n) return;
        const float* xr = &sX[(threadIdx.x >> 4) * FF];
        float acc = 0.0f;
#pragma unroll
        for (int k = 0; k < FF; k++) acc = fmaf(xr[k], sW[k * CC + c], acc);
        g_y[node * CC + c]   = acc;
        g_agg[node * CC + c] = acc;     // self-loop contribution
    } else {
        int b = blockIdx.x - projBlocks;
        int base = b * 2048;            // 8 edges per thread
        if (g_is64) {
            const long long* dl = (const long long*)ei + E;
#pragma unroll
            for (int k = 0; k < 8; k++) {
                int e = base + k * 256 + threadIdx.x;
                if (e < E) atomicAdd(&g_degi[(int)__ldg(&dl[e])], 1);
            }
        } else {
            const int* dl = (const int*)ei + E;
#pragma unroll
            for (int k = 0; k < 8; k++) {
                int e = base + k * 256 + threadIdx.x;
                if (e < E) atomicAdd(&g_degi[__ldg(&dl[e])], 1);
            }
        }
    }
}

// ---------------- edge scatter, 4 lanes per edge ----------------
__device__ __forceinline__ void red4(float* addr, float4 v) {
    asm volatile("red.global.add.v4.f32 [%0], {%1,%2,%3,%4};"
                 :: "l"(addr), "f"(v.x), "f"(v.y), "f"(v.z), "f"(v.w) : "memory");
}

__global__ void k_edge(const void* __restrict__ ei, int E) {
    int t = blockIdx.x * blockDim.x + threadIdx.x;
    int e = t >> 2;            // edge id
    int q = t & 3;             // which float4 of the 16-float row
    if (e >= E) return;
    int src, dst;
    if (g_is64) {
        const long long* p = (const long long*)ei;
        src = (int)__ldg(&p[e]);
        dst = (int)__ldg(&p[E + e]);
    } else {
        const int* p = (const int*)ei;
        src = __ldg(&p[e]);
        dst = __ldg(&p[E + e]);
    }
    float4 v = __ldg((const float4*)&g_y[src * CC + q * 4]);
    red4(&g_agg[dst * CC + q * 4], v);
}

// ---------------- head: mean + bias + relu, MLP, sigmoid, weighted BCE ----------------
__global__ void k_head(const float* __restrict__ bias,
                       const float* __restrict__ l1w,  // [16,8]
                       const float* __restrict__ l1b,
                       const float* __restrict__ ow,   // [8,1]
                       const float* __restrict__ ob,
                       const float* __restrict__ labels,
                       const float* __restrict__ wts,
                       float* __restrict__ pout, float* losss,
                       int n, float inv_n) {
    __shared__ float sb[CC], sl1w[CC * L1], sl1b[L1], sow[L1], sob;
    if (threadIdx.x < CC) sb[threadIdx.x] = bias[threadIdx.x];
    if (threadIdx.x < CC * L1) sl1w[threadIdx.x] = l1w[threadIdx.x];
    if (threadIdx.x < L1) { sl1b[threadIdx.x] = l1b[threadIdx.x]; sow[threadIdx.x] = ow[threadIdx.x]; }
    if (threadIdx.x == 0) sob = ob[0];
    __syncthreads();

    int i = blockIdx.x * blockDim.x + threadIdx.x;
    float term = 0.0f;
    if (i < n) {
        float invdeg = 1.0f / (float)g_degi[i];
        const float4* ar = (const float4*)&g_agg[i * CC];
        float4 v0 = ar[0], v1 = ar[1], v2 = ar[2], v3 = ar[3];
        float h[CC] = {v0.x, v0.y, v0.z, v0.w, v1.x, v1.y, v1.z, v1.w,
                       v2.x, v2.y, v2.z, v2.w, v3.x, v3.y, v3.z, v3.w};
#pragma unroll
        for (int c = 0; c < CC; c++) h[c] = fmaxf(fmaf(h[c], invdeg, sb[c]), 0.0f);

        float h2[L1];
#pragma unroll
        for (int j = 0; j < L1; j++) {
            float s = sl1b[j];
#pragma unroll
            for (int c = 0; c < CC; c++) s = fmaf(h[c], sl1w[c * L1 + j], s);
            h2[j] = fmaxf(s, 0.0f);
        }
        float z = sob;
#pragma unroll
        for (int j = 0; j < L1; j++) z = fmaf(h2[j], sow[j], z);
        float p = 1.0f / (1.0f + __expf(-z));
        pout[i] = p;

        const float eps = 1e-7f;
        float pc = fminf(fmaxf(p, eps), 1.0f - eps);
        // labels are exactly 0/1 -> single log
        float sel = (labels[i] > 0.5f) ? pc : (1.0f - pc);
        term = wts[i] * (-__logf(sel)) * inv_n;
    }
    // block reduce
#pragma unroll
    for (int off = 16; off > 0; off >>= 1)
        term += __shfl_down_sync(0xFFFFFFFFu, term, off);
    __shared__ float wsum[8];
    int wid = threadIdx.x >> 5, lid = threadIdx.x & 31;
    if (lid == 0) wsum[wid] = term;
    __syncthreads();
    if (threadIdx.x == 0 && losss) {
        float s = 0.0f;
#pragma unroll
        for (int k = 0; k < (int)(blockDim.x >> 5); k++) s += wsum[k];
        atomicAdd(losss, s);
    }
}

// ---------------- launch ----------------
extern "C" void kernel_launch(void* const* d_in, const int* in_sizes, int n_in,
                              void* d_out, int out_size) {
    const float* x      = (const float*)d_in[0];
    const void*  ei     = d_in[1];
    const float* labels = (const float*)d_in[2];
    const float* wts    = (const float*)d_in[3];
    const float* W      = (const float*)d_in[4];
    // d_in[5]=u, d_in[6]=c unused (H=1 softmax == 1)
    const float* bias   = (const float*)d_in[7];
    const float* l1w    = (const float*)d_in[8];
    const float* l1b    = (const float*)d_in[9];
    const float* ow     = (const float*)d_in[10];
    const float* ob     = (const float*)d_in[11];

    int n = in_sizes[0] / FF;
    int E = in_sizes[1] / 2;

    float* out = (float*)d_out;
    int loss_slot = (out_size == n + 1) ? 1 : 0;
    float* pout  = loss_slot ? (out + 1) : out;
    float* losss = loss_slot ? out : (float*)0;

    int projBlocks = (n + 15) / 16;
    int histBlocks = (E + 2047) / 2048;

    k_detect<<<(n + 255) / 256, 256>>>((const unsigned*)ei, losss, n);
    k_proj_hist<<<projBlocks + histBlocks, 256>>>(x, W, ei, n, E, projBlocks);
    long long threads = (long long)E * 4;
    k_edge<<<(int)((threads + 255) / 256), 256>>>(ei, E);
    k_head<<<(n + 255) / 256, 256>>>(bias, l1w, l1b, ow, ob, labels, wts,
                                     pout, losss, n, 1.0f / (float)n);
}

// round 5
// speedup vs baseline: 1.1130x; 1.1130x over previous
#include <cuda_runtime.h>
#include <cuda_fp16.h>
#include <math.h>

#define NN 50000
#define FF 48
#define CC 16     // H*C1 with H=1 -> softmax == 1, attention vanishes
#define L1 8

// ---------------- device scratch ----------------
__device__ __align__(32) __half g_yh[NN * CC];    // x @ W  (fp16)
__device__ __align__(32) __half g_aggh[NN * CC];  // fp16 segment sum (self loop preloaded)
__device__ int   g_degi[NN];                      // in-degree + 1 (self loop)
__device__ int   g_is64;

// ---------------- detect edge dtype + init deg + zero loss slot ----------------
// int64 node ids < 50000 => every odd 32-bit word of the first 1024 entries is 0.
__global__ void k_detect(const unsigned* __restrict__ ew, float* losss, int n) {
    int i = blockIdx.x * blockDim.x + threadIdx.x;
    if (i < n) g_degi[i] = 1;                 // self loop
    if (blockIdx.x == 0) {
        __shared__ unsigned any;
        if (threadIdx.x == 0) any = 0u;
        __syncthreads();
        unsigned v = 0u;
        for (int k = threadIdx.x; k < 1024; k += blockDim.x) v |= ew[2 * k + 1];
        if (v) atomicOr(&any, 1u);
        __syncthreads();
        if (threadIdx.x == 0) {
            g_is64 = (any == 0u) ? 1 : 0;
            if (losss) *losss = 0.0f;
        }
    }
}

// ---------------- fused: projection y = x @ W (smem-staged) + deg histogram ----------------
__global__ void k_proj_hist(const float* __restrict__ x, const float* __restrict__ W,
                            const void* __restrict__ ei, int n, int E, int projBlocks) {
    if ((int)blockIdx.x < projBlocks) {
        __shared__ float sW[FF * CC];   // 3 KB
        __shared__ float sX[16 * FF];   // 3 KB
        for (int i = threadIdx.x; i < FF * CC; i += blockDim.x) sW[i] = W[i];
        int nodeBase = blockIdx.x * 16;
        for (int i = threadIdx.x; i < 16 * FF; i += blockDim.x) {
            int g = nodeBase * FF + i;
            sX[i] = (g < n * FF) ? x[g] : 0.0f;
        }
        __syncthreads();
        int node = nodeBase + (threadIdx.x >> 4);
        int c    = threadIdx.x & 15;
        if (node >= n) return;
        const float* xr = &sX[(threadIdx.x >> 4) * FF];
        float acc = 0.0f;
#pragma unroll
        for (int k = 0; k < FF; k++) acc = fmaf(xr[k], sW[k * CC + c], acc);
        __half hv = __float2half(acc);
        g_yh[node * CC + c]   = hv;
        g_aggh[node * CC + c] = hv;     // self-loop contribution
    } else {
        int b = blockIdx.x - projBlocks;
        int base = b * 1024;            // 4 edges per thread
        if (g_is64) {
            const long long* dl = (const long long*)ei + E;
#pragma unroll
            for (int k = 0; k < 4; k++) {
                int e = base + k * 256 + threadIdx.x;
                if (e < E) atomicAdd(&g_degi[(int)__ldg(&dl[e])], 1);
            }
        } else {
            const int* dl = (const int*)ei + E;
#pragma unroll
            for (int k = 0; k < 4; k++) {
                int e = base + k * 256 + threadIdx.x;
                if (e < E) atomicAdd(&g_degi[__ldg(&dl[e])], 1);
            }
        }
    }
}

// ---------------- edge scatter, 2 lanes per edge, fp16 vector RED ----------------
__device__ __forceinline__ void red_h8(__half* addr, uint4 v) {
    asm volatile("red.global.add.noftz.v4.f16x2 [%0], {%1,%2,%3,%4};"
                 :: "l"(addr), "r"(v.x), "r"(v.y), "r"(v.z), "r"(v.w) : "memory");
}

__global__ void k_edge(const void* __restrict__ ei, int E) {
    int t = blockIdx.x * blockDim.x + threadIdx.x;
    int e = t >> 1;            // edge id
    int q = t & 1;             // which 16B half-row (8 halves)
    if (e >= E) return;
    int src, dst;
    if (g_is64) {
        const long long* p = (const long long*)ei;
        src = (int)__ldg(&p[e]);
        dst = (int)__ldg(&p[E + e]);
    } else {
        const int* p = (const int*)ei;
        src = __ldg(&p[e]);
        dst = __ldg(&p[E + e]);
    }
    uint4 v = __ldg((const uint4*)&g_yh[src * CC + q * 8]);
    red_h8(&g_aggh[dst * CC + q * 8], v);
}

// ---------------- head: mean + bias + relu, MLP, sigmoid, weighted BCE ----------------
__global__ void k_head(const float* __restrict__ bias,
                       const float* __restrict__ l1w,  // [16,8]
                       const float* __restrict__ l1b,
                       const float* __restrict__ ow,   // [8,1]
                       const float* __restrict__ ob,
                       const float* __restrict__ labels,
                       const float* __restrict__ wts,
                       float* __restrict__ pout, float* losss,
                       int n, float inv_n) {
    __shared__ float sb[CC], sl1w[CC * L1], sl1b[L1], sow[L1], sob;
    if (threadIdx.x < CC) sb[threadIdx.x] = bias[threadIdx.x];
    if (threadIdx.x < CC * L1) sl1w[threadIdx.x] = l1w[threadIdx.x];
    if (threadIdx.x < L1) { sl1b[threadIdx.x] = l1b[threadIdx.x]; sow[threadIdx.x] = ow[threadIdx.x]; }
    if (threadIdx.x == 0) sob = ob[0];
    __syncthreads();

    int i = blockIdx.x * blockDim.x + threadIdx.x;
    float term = 0.0f;
    if (i < n) {
        // issue independent loads early
        float lab = labels[i];
        float wt  = wts[i];
        float invdeg = 1.0f / (float)g_degi[i];
        const uint4* ar = (const uint4*)&g_aggh[i * CC];
        uint4 r0 = ar[0], r1 = ar[1];
        float h[CC];
        {
            const unsigned rr[8] = {r0.x, r0.y, r0.z, r0.w, r1.x, r1.y, r1.z, r1.w};
#pragma unroll
            for (int k = 0; k < 8; k++) {
                float2 f = __half22float2(*(const __half2*)&rr[k]);
                h[2 * k]     = f.x;
                h[2 * k + 1] = f.y;
            }
        }
#pragma unroll
        for (int c = 0; c < CC; c++) h[c] = fmaxf(fmaf(h[c], invdeg, sb[c]), 0.0f);

        float h2[L1];
#pragma unroll
        for (int j = 0; j < L1; j++) {
            float s = sl1b[j];
#pragma unroll
            for (int c = 0; c < CC; c++) s = fmaf(h[c], sl1w[c * L1 + j], s);
            h2[j] = fmaxf(s, 0.0f);
        }
        float z = sob;
#pragma unroll
        for (int j = 0; j < L1; j++) z = fmaf(h2[j], sow[j], z);
        float p = 1.0f / (1.0f + __expf(-z));
        pout[i] = p;

        const float eps = 1e-7f;
        float pc = fminf(fmaxf(p, eps), 1.0f - eps);
        // labels are exactly 0/1 -> single log
        float sel = (lab > 0.5f) ? pc : (1.0f - pc);
        term = wt * (-__logf(sel)) * inv_n;
    }
    // block reduce
#pragma unroll
    for (int off = 16; off > 0; off >>= 1)
        term += __shfl_down_sync(0xFFFFFFFFu, term, off);
    __shared__ float wsum[8];
    int wid = threadIdx.x >> 5, lid = threadIdx.x & 31;
    if (lid == 0) wsum[wid] = term;
    __syncthreads();
    if (threadIdx.x == 0 && losss) {
        float s = 0.0f;
#pragma unroll
        for (int k = 0; k < (int)(blockDim.x >> 5); k++) s += wsum[k];
        atomicAdd(losss, s);
    }
}

// ---------------- launch ----------------
extern "C" void kernel_launch(void* const* d_in, const int* in_sizes, int n_in,
                              void* d_out, int out_size) {
    const float* x      = (const float*)d_in[0];
    const void*  ei     = d_in[1];
    const float* labels = (const float*)d_in[2];
    const float* wts    = (const float*)d_in[3];
    const float* W      = (const float*)d_in[4];
    // d_in[5]=u, d_in[6]=c unused (H=1 softmax == 1)
    const float* bias   = (const float*)d_in[7];
    const float* l1w    = (const float*)d_in[8];
    const float* l1b    = (const float*)d_in[9];
    const float* ow     = (const float*)d_in[10];
    const float* ob     = (const float*)d_in[11];

    int n = in_sizes[0] / FF;
    int E = in_sizes[1] / 2;

    float* out = (float*)d_out;
    int loss_slot = (out_size == n + 1) ? 1 : 0;
    float* pout  = loss_slot ? (out + 1) : out;
    float* losss = loss_slot ? out : (float*)0;

    int projBlocks = (n + 15) / 16;
    int histBlocks = (E + 1023) / 1024;

    k_detect<<<(n + 255) / 256, 256>>>((const unsigned*)ei, losss, n);
    k_proj_hist<<<projBlocks + histBlocks, 256>>>(x, W, ei, n, E, projBlocks);
    long long threads = (long long)E * 2;
    k_edge<<<(int)((threads + 511) / 512), 512>>>(ei, E);
    k_head<<<(n + 255) / 256, 256>>>(bias, l1w, l1b, ow, ob, labels, wts,
                                     pout, losss, n, 1.0f / (float)n);
}